// round 9
// baseline (speedup 1.0000x reference)
#include <cuda_runtime.h>
#include <stdint.h>

#define HH 128
#define WW 160
#define HWSZ (HH * WW)          // 20480
#define BMAX 4
#define FLOW_SCALE 160.0f

#define TBITS 20
#define TSIZE (1u << TBITS)
#define TMASK (TSIZE - 1u)
__device__ uint32_t g_hash[(size_t)BMAX * TSIZE];         // 16 MB, L2-resident
// Packed accumulator: low 32 = event count, high 32 = distinct-src count.
__device__ unsigned long long g_acc[BMAX * 2 * HWSZ];     // 1.25 MB
__device__ float2   g_flow2[BMAX * HWSZ];                 // interleaved (fx, fy)

// ---------------------------------------------------------------------------
// Zero hash + acc, build interleaved flow (identical to R4).
// ---------------------------------------------------------------------------
__global__ void prep_kernel(const float* __restrict__ flow, int B) {
    size_t tid  = (size_t)blockIdx.x * blockDim.x + threadIdx.x;
    size_t nthr = (size_t)gridDim.x * blockDim.x;

    uint4* hm = reinterpret_cast<uint4*>(g_hash);
    const size_t n4 = ((size_t)BMAX * TSIZE) / 4;
    uint4 z4 = make_uint4(0u, 0u, 0u, 0u);
    for (size_t i = tid; i < n4; i += nthr) hm[i] = z4;

    ulonglong2* am = reinterpret_cast<ulonglong2*>(g_acc);
    const size_t na = ((size_t)BMAX * 2 * HWSZ) / 2;
    for (size_t i = tid; i < na; i += nthr) am[i] = make_ulonglong2(0ull, 0ull);

    size_t nflow = (size_t)B * HWSZ;
    for (size_t i = tid; i < nflow; i += nthr) {
        size_t b = i / HWSZ, j = i % HWSZ;
        const float* fb = flow + b * 2 * HWSZ;
        g_flow2[i] = make_float2(fb[j], fb[HWSZ + j]);  // (fx, fy)
    }
}

// ---------------------------------------------------------------------------
// Per-event: R4 body, but batch = blockIdx.y (no i/N division; L1-friendly
// per-batch flow locality).
// ---------------------------------------------------------------------------
__global__ void __launch_bounds__(256)
event_kernel(const float4* __restrict__ events, int N) {
    const int b = blockIdx.y;
    const int base = (blockIdx.x * blockDim.x + threadIdx.x) * 2;

    const float4* ev = events + (size_t)b * N;
    const float2* fl = g_flow2 + (size_t)b * HWSZ;
    uint32_t* tbl = g_hash + ((size_t)b << TBITS);
    unsigned long long* accb = g_acc + (size_t)b * 2 * HWSZ;

#pragma unroll
    for (int k = 0; k < 2; k++) {
        int i = base + k;
        if (i >= N) return;

        float4 e = ev[i];               // (t, y, x, p)
        float t = e.x, y = e.y, x = e.z, p = e.w;

        int src = (int)(__fadd_rn(__fmul_rn(y, (float)WW), x));

        float2 f = __ldg(&fl[src]);     // (fx, fy)

        // warped = yx + (1-t) * flow * 160  (exact ref op order, no FMA)
        float s  = __fadd_rn(1.0f, -t);
        float wy = __fadd_rn(y, __fmul_rn(__fmul_rn(s, f.y), FLOW_SCALE));
        float wx = __fadd_rn(x, __fmul_rn(__fmul_rn(s, f.x), FLOW_SCALE));

        // jnp.round == round half to even == rintf
        float ry = rintf(wy);
        float rx = rintf(wx);

        if (!(ry >= 0.0f && ry < (float)HH && rx >= 0.0f && rx < (float)WW))
            continue;

        int fw = (int)ry * WW + (int)rx;
        int c  = (p > 0.0f) ? 0 : 1;

        // hash dedup: direct CAS (slots go 0 -> tag exactly once)
        uint32_t key = ((uint32_t)c << 30) | ((uint32_t)src << 15) | (uint32_t)fw;
        uint32_t tag = key + 1u;
        uint32_t h   = (key * 2654435761u) >> (32 - TBITS);

        unsigned long long inc = 1ull;
        while (true) {
            uint32_t old = atomicCAS(&tbl[h], 0u, tag);
            if (old == 0u) { inc = 0x100000001ull; break; }  // first occurrence
            if (old == tag) break;                           // duplicate
            h = (h + 1u) & TMASK;
        }

        atomicAdd(&accb[(size_t)c * HWSZ + fw], inc);
    }
}

// ---------------------------------------------------------------------------
// Final: out = contrib>0 ? cnt/contrib : 0
// ---------------------------------------------------------------------------
__global__ void div_kernel(float* __restrict__ out, int n) {
    int i = blockIdx.x * blockDim.x + threadIdx.x;
    if (i >= n) return;
    unsigned long long v = g_acc[i];
    uint32_t cnt = (uint32_t)v;
    uint32_t ctb = (uint32_t)(v >> 32);
    out[i] = (ctb > 0u) ? ((float)cnt / (float)ctb) : 0.0f;
}

extern "C" void kernel_launch(void* const* d_in, const int* in_sizes, int n_in,
                              void* d_out, int out_size) {
    const float*  flow   = (const float*)d_in[0];   // (B, 2, H, W)
    const float4* events = (const float4*)d_in[1];  // (B, N, 4)
    float* out = (float*)d_out;                     // (B, 2, H, W)

    int B = in_sizes[0] / (2 * HWSZ);
    if (B > BMAX) B = BMAX;
    int N = in_sizes[1] / (4 * B);

    prep_kernel<<<4096, 256>>>(flow, B);

    dim3 grid((N + 511) / 512, B);
    event_kernel<<<grid, 256>>>(events, N);

    int dn = B * 2 * HWSZ;
    div_kernel<<<(dn + 255) / 256, 256>>>(out, dn);
}